// round 13
// baseline (speedup 1.0000x reference)
#include <cuda_runtime.h>
#include <cuda_bf16.h>
#include <cstdint>

// ---------------------------------------------------------------------------
// out[32,1024] = concat_c( spatial_mean(feat_l) ) @ conv_w.T
// (bilinear half-pixel upsample at ratios 1,2,4,8 + mean == plain mean.)
// feat0 [32,256,56,56], feat1 [32,512,28,28], feat2 [32,1024,14,14],
// feat3 [32,2048,7,7], conv_w [1024,3840].
//
// Sequential 3-kernel pipeline (overlap designs falsified in R10-R12):
//  1) fused pool (HBM roofline, ~31us)
//  2) GEMM stage-1: stream W via __ldg (no W smem), v in smem read as
//     warp-broadcasts, 4b x 4e f32x2 microtile, NO atomics — writes
//     disjoint split-K partials (coalesced STG, lands in L2)
//  3) stage-2: sum 60 partials per output from L2 (~1.5us)
// ---------------------------------------------------------------------------

#define BATCH 32
#define CTOT  3840
#define EMB   1024

#define KSPLIT 60
#define KTILE  64        // 60 * 64 = 3840

__device__ float g_v[BATCH * CTOT];                 // pooled vector
__device__ float g_part[KSPLIT][BATCH][EMB];        // split-K partials (7.9MB)

__device__ __forceinline__ float warp_reduce(float s) {
    #pragma unroll
    for (int o = 16; o > 0; o >>= 1)
        s += __shfl_down_sync(0xFFFFFFFFu, s, o);
    return s;
}

__device__ __forceinline__ void ffma2(unsigned long long& d,
                                      unsigned long long a,
                                      unsigned long long b) {
    asm("fma.rn.f32x2 %0, %1, %2, %0;" : "+l"(d) : "l"(a), "l"(b));
}

// ---------------------------------------------------------------------------
// Fused pooling kernel (R3/R9 version — at HBM roofline).
// ---------------------------------------------------------------------------
#define NBLK0 1024
#define NBLK1 1024
#define NBLK2 2048
#define NBLK3 2048
#define NBLK_TOTAL (NBLK0 + NBLK1 + NBLK2 + NBLK3)

__global__ __launch_bounds__(256)
void fused_pool_kernel(const float* __restrict__ f0,
                       const float* __restrict__ f1,
                       const float* __restrict__ f2,
                       const float* __restrict__ f3) {
    const int blk  = blockIdx.x;
    const int lane = threadIdx.x & 31;
    const int warp = threadIdx.x >> 5;

    if (blk < NBLK0) {
        // ---- level 0: 56x56 = 784 f4, 1 plane per warp ----
        const int plane = blk * 8 + warp;
        const float4* __restrict__ p = (const float4*)f0 + (size_t)plane * 784;
        float a0 = 0.f, a1 = 0.f, a2 = 0.f, a3 = 0.f;
        #pragma unroll
        for (int k = 0; k < 6; k++) {
            float4 v0 = p[lane + (4 * k + 0) * 32];
            float4 v1 = p[lane + (4 * k + 1) * 32];
            float4 v2 = p[lane + (4 * k + 2) * 32];
            float4 v3 = p[lane + (4 * k + 3) * 32];
            a0 += (v0.x + v0.y) + (v0.z + v0.w);
            a1 += (v1.x + v1.y) + (v1.z + v1.w);
            a2 += (v2.x + v2.y) + (v2.z + v2.w);
            a3 += (v3.x + v3.y) + (v3.z + v3.w);
        }
        if (lane < 16) {
            float4 v = p[768 + lane];
            a0 += (v.x + v.y) + (v.z + v.w);
        }
        float s = warp_reduce((a0 + a1) + (a2 + a3));
        if (lane == 0) {
            const int b = plane >> 8, c = plane & 255;      // C=256
            g_v[b * CTOT + c] = s * (1.f / 3136.f);
        }
    } else if (blk < NBLK0 + NBLK1) {
        // ---- level 1: 28x28 = 196 f4, 2 planes per warp ----
        const int g = (blk - NBLK0) * 8 + warp;
        const int plane0 = g * 2;
        const float4* __restrict__ p = (const float4*)f1 + (size_t)plane0 * 196;
        float s0 = 0.f, s1 = 0.f;
        #pragma unroll
        for (int k = 0; k < 6; k++) {
            float4 v0 = p[lane + k * 32];
            float4 v1 = p[196 + lane + k * 32];
            s0 += (v0.x + v0.y) + (v0.z + v0.w);
            s1 += (v1.x + v1.y) + (v1.z + v1.w);
        }
        if (lane < 4) {
            float4 v0 = p[192 + lane];
            float4 v1 = p[196 + 192 + lane];
            s0 += (v0.x + v0.y) + (v0.z + v0.w);
            s1 += (v1.x + v1.y) + (v1.z + v1.w);
        }
        s0 = warp_reduce(s0);
        s1 = warp_reduce(s1);
        if (lane == 0) {
            const int b = plane0 >> 9, c = plane0 & 511;    // C=512
            g_v[b * CTOT + 256 + c]     = s0 * (1.f / 784.f);
            g_v[b * CTOT + 256 + c + 1] = s1 * (1.f / 784.f);
        }
    } else if (blk < NBLK0 + NBLK1 + NBLK2) {
        // ---- level 2: 14x14 = 49 f4, 2 planes per warp ----
        const int g = (blk - NBLK0 - NBLK1) * 8 + warp;
        const int plane0 = g * 2;
        const float4* __restrict__ p = (const float4*)f2 + (size_t)plane0 * 49;
        float s0, s1;
        {
            float4 v0 = p[lane];
            float4 v1 = p[49 + lane];
            s0 = (v0.x + v0.y) + (v0.z + v0.w);
            s1 = (v1.x + v1.y) + (v1.z + v1.w);
        }
        if (lane < 17) {
            float4 v0 = p[32 + lane];
            float4 v1 = p[49 + 32 + lane];
            s0 += (v0.x + v0.y) + (v0.z + v0.w);
            s1 += (v1.x + v1.y) + (v1.z + v1.w);
        }
        s0 = warp_reduce(s0);
        s1 = warp_reduce(s1);
        if (lane == 0) {
            const int b = plane0 >> 10, c = plane0 & 1023;  // C=1024
            g_v[b * CTOT + 768 + c]     = s0 * (1.f / 196.f);
            g_v[b * CTOT + 768 + c + 1] = s1 * (1.f / 196.f);
        }
    } else {
        // ---- level 3: 7x7 planes; warp handles 4 planes = 49 f4 ----
        const int g = (blk - NBLK0 - NBLK1 - NBLK2) * 8 + warp;
        const float4* __restrict__ p = (const float4*)f3 + (size_t)g * 49;

        float a0 = 0.f, a1 = 0.f, a2 = 0.f, a3 = 0.f;
        #pragma unroll
        for (int rep = 0; rep < 2; rep++) {
            const int i = lane + rep * 32;
            if (i < 49) {
                float4 v = p[i];
                const int e = 4 * i;
                {
                    int pl = e / 49; float x = v.x;
                    if (pl == 0) a0 += x; else if (pl == 1) a1 += x;
                    else if (pl == 2) a2 += x; else a3 += x;
                }
                {
                    int pl = (e + 1) / 49; float x = v.y;
                    if (pl == 0) a0 += x; else if (pl == 1) a1 += x;
                    else if (pl == 2) a2 += x; else a3 += x;
                }
                {
                    int pl = (e + 2) / 49; float x = v.z;
                    if (pl == 0) a0 += x; else if (pl == 1) a1 += x;
                    else if (pl == 2) a2 += x; else a3 += x;
                }
                {
                    int pl = (e + 3) / 49; float x = v.w;
                    if (pl == 0) a0 += x; else if (pl == 1) a1 += x;
                    else if (pl == 2) a2 += x; else a3 += x;
                }
            }
        }
        a0 = warp_reduce(a0);
        a1 = warp_reduce(a1);
        a2 = warp_reduce(a2);
        a3 = warp_reduce(a3);
        if (lane == 0) {
            const int plane0 = g * 4;
            const int b = plane0 >> 11, c = plane0 & 2047;  // C=2048
            float* dst = &g_v[b * CTOT + 1792 + c];
            dst[0] = a0 * (1.f / 49.f);
            dst[1] = a1 * (1.f / 49.f);
            dst[2] = a2 * (1.f / 49.f);
            dst[3] = a3 * (1.f / 49.f);
        }
    }
}

// ---------------------------------------------------------------------------
// GEMM stage-1: grid (8 e-tiles x 60 k-splits) = 480 blocks x 256 threads
// (26 warps/SM). Tile 128e x 64k. W streamed via __ldg (no smem staging),
// v slice in smem read as warp-uniform broadcasts. Thread microtile 4b x 4e
// with f32x2 along K. Writes disjoint partials (coalesced STG) — no atomics.
// ---------------------------------------------------------------------------
__global__ __launch_bounds__(256)
void gemm_part_kernel(const float* __restrict__ w) {
    __shared__ float vs[32][68];

    const int e0   = blockIdx.x * 128;
    const int ks   = blockIdx.y;
    const int k0   = ks * KTILE;
    const int tid  = threadIdx.x;
    const int lane = tid & 31;
    const int warp = tid >> 5;

    // load v slice [32][64]: 512 f4, 2 per thread
    #pragma unroll
    for (int r = 0; r < 2; r++) {
        const int i  = tid + r * 256;
        const int b  = i >> 4;
        const int kq = i & 15;
        float4 v4 = *(const float4*)&g_v[b * CTOT + k0 + kq * 4];
        *(float4*)&vs[b][kq * 4] = v4;
    }
    __syncthreads();

    const int b0 = warp * 4;   // 8 warps x 4b = 32 b

    // thread e-columns: e0 + lane + 32*j, j = 0..3 (lane-contiguous)
    const float* wr0 = w + (size_t)(e0 + lane +  0) * CTOT + k0;
    const float* wr1 = w + (size_t)(e0 + lane + 32) * CTOT + k0;
    const float* wr2 = w + (size_t)(e0 + lane + 64) * CTOT + k0;
    const float* wr3 = w + (size_t)(e0 + lane + 96) * CTOT + k0;

    unsigned long long acc[4][4];   // [b_i][e_j], f32x2-packed along K
    #pragma unroll
    for (int i = 0; i < 4; i++)
        #pragma unroll
        for (int j = 0; j < 4; j++) acc[i][j] = 0ull;

    #pragma unroll
    for (int k4 = 0; k4 < 16; k4++) {
        float4 wv[4];
        wv[0] = __ldg((const float4*)wr0 + k4);
        wv[1] = __ldg((const float4*)wr1 + k4);
        wv[2] = __ldg((const float4*)wr2 + k4);
        wv[3] = __ldg((const float4*)wr3 + k4);
        #pragma unroll
        for (int i = 0; i < 4; i++) {
            float4 av = *(const float4*)&vs[b0 + i][k4 * 4];   // broadcast
            const unsigned long long* ap = (const unsigned long long*)&av;
            #pragma unroll
            for (int j = 0; j < 4; j++) {
                const unsigned long long* wp = (const unsigned long long*)&wv[j];
                ffma2(acc[i][j], ap[0], wp[0]);
                ffma2(acc[i][j], ap[1], wp[1]);
            }
        }
    }

    // write partials: lanes contiguous in e -> coalesced STG.32
    #pragma unroll
    for (int i = 0; i < 4; i++) {
        #pragma unroll
        for (int j = 0; j < 4; j++) {
            float2 r2 = *(const float2*)&acc[i][j];
            g_part[ks][b0 + i][e0 + lane + 32 * j] = r2.x + r2.y;
        }
    }
}

// ---------------------------------------------------------------------------
// GEMM stage-2: sum the 60 partials per output (all L2-resident).
// 32768 outputs, 128 blocks x 256 threads, coalesced within each partial.
// ---------------------------------------------------------------------------
__global__ __launch_bounds__(256)
void gemm_reduce_kernel(float* __restrict__ out) {
    const int idx = blockIdx.x * 256 + threadIdx.x;   // 0..32767
    const int b = idx >> 10;
    const int e = idx & 1023;
    float s = 0.f;
    #pragma unroll
    for (int k = 0; k < KSPLIT; k++)
        s += g_part[k][b][e];
    out[idx] = s;
}

// ---------------------------------------------------------------------------
extern "C" void kernel_launch(void* const* d_in, const int* in_sizes, int n_in,
                              void* d_out, int out_size) {
    const float* feat0  = (const float*)d_in[0];
    const float* feat1  = (const float*)d_in[1];
    const float* feat2  = (const float*)d_in[2];
    const float* feat3  = (const float*)d_in[3];
    const float* conv_w = (const float*)d_in[4];
    float* out = (float*)d_out;

    fused_pool_kernel<<<NBLK_TOTAL, 256>>>(feat0, feat1, feat2, feat3);

    gemm_part_kernel<<<dim3(8, KSPLIT), 256>>>(conv_w);

    gemm_reduce_kernel<<<128, 256>>>(out);
}

// round 14
// speedup vs baseline: 1.5652x; 1.5652x over previous
#include <cuda_runtime.h>
#include <cuda_bf16.h>
#include <cstdint>

// ---------------------------------------------------------------------------
// out[32,1024] = concat_c( spatial_mean(feat_l) ) @ conv_w.T
// (bilinear half-pixel upsample at ratios 1,2,4,8 + mean == plain mean.)
// feat0 [32,256,56,56], feat1 [32,512,28,28], feat2 [32,1024,14,14],
// feat3 [32,2048,7,7], conv_w [1024,3840].
//
// Sequential 3-kernel pipeline:
//  1) fused pool (HBM roofline, ~33us)
//  2) GEMM stage-1: COALESCED cp.async W->smem (R13's lane-per-row __ldg
//     streaming was fully uncoalesced — reverted), 256-thr blocks
//     (24 warps/SM), f32x2 4b x 4e microtile, split-K partials (no atomics)
//  3) stage-2: sum 60 L2-resident partials per output
// ---------------------------------------------------------------------------

#define BATCH 32
#define CTOT  3840
#define EMB   1024

#define KSPLIT 60
#define KTILE  64
#define PITCH  68          // 68 mod 32 = 4 -> conflict-free LDS.128 phases

__device__ float g_v[BATCH * CTOT];                 // pooled vector
__device__ float g_part[KSPLIT][BATCH][EMB];        // split-K partials (7.9MB)

__device__ __forceinline__ float warp_reduce(float s) {
    #pragma unroll
    for (int o = 16; o > 0; o >>= 1)
        s += __shfl_down_sync(0xFFFFFFFFu, s, o);
    return s;
}

__device__ __forceinline__ void ffma2(unsigned long long& d,
                                      unsigned long long a,
                                      unsigned long long b) {
    asm("fma.rn.f32x2 %0, %1, %2, %0;" : "+l"(d) : "l"(a), "l"(b));
}

// ---------------------------------------------------------------------------
// Fused pooling kernel (unchanged — measured 75.5% DRAM).
// ---------------------------------------------------------------------------
#define NBLK0 1024
#define NBLK1 1024
#define NBLK2 2048
#define NBLK3 2048
#define NBLK_TOTAL (NBLK0 + NBLK1 + NBLK2 + NBLK3)

__global__ __launch_bounds__(256)
void fused_pool_kernel(const float* __restrict__ f0,
                       const float* __restrict__ f1,
                       const float* __restrict__ f2,
                       const float* __restrict__ f3) {
    const int blk  = blockIdx.x;
    const int lane = threadIdx.x & 31;
    const int warp = threadIdx.x >> 5;

    if (blk < NBLK0) {
        // ---- level 0: 56x56 = 784 f4, 1 plane per warp ----
        const int plane = blk * 8 + warp;
        const float4* __restrict__ p = (const float4*)f0 + (size_t)plane * 784;
        float a0 = 0.f, a1 = 0.f, a2 = 0.f, a3 = 0.f;
        #pragma unroll
        for (int k = 0; k < 6; k++) {
            float4 v0 = p[lane + (4 * k + 0) * 32];
            float4 v1 = p[lane + (4 * k + 1) * 32];
            float4 v2 = p[lane + (4 * k + 2) * 32];
            float4 v3 = p[lane + (4 * k + 3) * 32];
            a0 += (v0.x + v0.y) + (v0.z + v0.w);
            a1 += (v1.x + v1.y) + (v1.z + v1.w);
            a2 += (v2.x + v2.y) + (v2.z + v2.w);
            a3 += (v3.x + v3.y) + (v3.z + v3.w);
        }
        if (lane < 16) {
            float4 v = p[768 + lane];
            a0 += (v.x + v.y) + (v.z + v.w);
        }
        float s = warp_reduce((a0 + a1) + (a2 + a3));
        if (lane == 0) {
            const int b = plane >> 8, c = plane & 255;      // C=256
            g_v[b * CTOT + c] = s * (1.f / 3136.f);
        }
    } else if (blk < NBLK0 + NBLK1) {
        // ---- level 1: 28x28 = 196 f4, 2 planes per warp ----
        const int g = (blk - NBLK0) * 8 + warp;
        const int plane0 = g * 2;
        const float4* __restrict__ p = (const float4*)f1 + (size_t)plane0 * 196;
        float s0 = 0.f, s1 = 0.f;
        #pragma unroll
        for (int k = 0; k < 6; k++) {
            float4 v0 = p[lane + k * 32];
            float4 v1 = p[196 + lane + k * 32];
            s0 += (v0.x + v0.y) + (v0.z + v0.w);
            s1 += (v1.x + v1.y) + (v1.z + v1.w);
        }
        if (lane < 4) {
            float4 v0 = p[192 + lane];
            float4 v1 = p[196 + 192 + lane];
            s0 += (v0.x + v0.y) + (v0.z + v0.w);
            s1 += (v1.x + v1.y) + (v1.z + v1.w);
        }
        s0 = warp_reduce(s0);
        s1 = warp_reduce(s1);
        if (lane == 0) {
            const int b = plane0 >> 9, c = plane0 & 511;    // C=512
            g_v[b * CTOT + 256 + c]     = s0 * (1.f / 784.f);
            g_v[b * CTOT + 256 + c + 1] = s1 * (1.f / 784.f);
        }
    } else if (blk < NBLK0 + NBLK1 + NBLK2) {
        // ---- level 2: 14x14 = 49 f4, 2 planes per warp ----
        const int g = (blk - NBLK0 - NBLK1) * 8 + warp;
        const int plane0 = g * 2;
        const float4* __restrict__ p = (const float4*)f2 + (size_t)plane0 * 49;
        float s0, s1;
        {
            float4 v0 = p[lane];
            float4 v1 = p[49 + lane];
            s0 = (v0.x + v0.y) + (v0.z + v0.w);
            s1 = (v1.x + v1.y) + (v1.z + v1.w);
        }
        if (lane < 17) {
            float4 v0 = p[32 + lane];
            float4 v1 = p[49 + 32 + lane];
            s0 += (v0.x + v0.y) + (v0.z + v0.w);
            s1 += (v1.x + v1.y) + (v1.z + v1.w);
        }
        s0 = warp_reduce(s0);
        s1 = warp_reduce(s1);
        if (lane == 0) {
            const int b = plane0 >> 10, c = plane0 & 1023;  // C=1024
            g_v[b * CTOT + 768 + c]     = s0 * (1.f / 196.f);
            g_v[b * CTOT + 768 + c + 1] = s1 * (1.f / 196.f);
        }
    } else {
        // ---- level 3: 7x7 planes; warp handles 4 planes = 49 f4 ----
        const int g = (blk - NBLK0 - NBLK1 - NBLK2) * 8 + warp;
        const float4* __restrict__ p = (const float4*)f3 + (size_t)g * 49;

        float a0 = 0.f, a1 = 0.f, a2 = 0.f, a3 = 0.f;
        #pragma unroll
        for (int rep = 0; rep < 2; rep++) {
            const int i = lane + rep * 32;
            if (i < 49) {
                float4 v = p[i];
                const int e = 4 * i;
                {
                    int pl = e / 49; float x = v.x;
                    if (pl == 0) a0 += x; else if (pl == 1) a1 += x;
                    else if (pl == 2) a2 += x; else a3 += x;
                }
                {
                    int pl = (e + 1) / 49; float x = v.y;
                    if (pl == 0) a0 += x; else if (pl == 1) a1 += x;
                    else if (pl == 2) a2 += x; else a3 += x;
                }
                {
                    int pl = (e + 2) / 49; float x = v.z;
                    if (pl == 0) a0 += x; else if (pl == 1) a1 += x;
                    else if (pl == 2) a2 += x; else a3 += x;
                }
                {
                    int pl = (e + 3) / 49; float x = v.w;
                    if (pl == 0) a0 += x; else if (pl == 1) a1 += x;
                    else if (pl == 2) a2 += x; else a3 += x;
                }
            }
        }
        a0 = warp_reduce(a0);
        a1 = warp_reduce(a1);
        a2 = warp_reduce(a2);
        a3 = warp_reduce(a3);
        if (lane == 0) {
            const int plane0 = g * 4;
            const int b = plane0 >> 11, c = plane0 & 2047;  // C=2048
            float* dst = &g_v[b * CTOT + 1792 + c];
            dst[0] = a0 * (1.f / 49.f);
            dst[1] = a1 * (1.f / 49.f);
            dst[2] = a2 * (1.f / 49.f);
            dst[3] = a3 * (1.f / 49.f);
        }
    }
}

// ---------------------------------------------------------------------------
// GEMM stage-1: grid (8 e-tiles, 60 k-splits) = 480 blocks x 256 threads.
// Tile 128e x 64k. Coalesced cp.async W->smem + v load, one wait.
// Compute: warp=4b, lane=4e, f32x2 along K; ws LDS.128 conflict-free,
// vs reads warp-broadcast. Disjoint partial outputs (no atomics).
// ---------------------------------------------------------------------------
__global__ __launch_bounds__(256)
void gemm_part_kernel(const float* __restrict__ w) {
    __shared__ float ws[128 * PITCH];
    __shared__ float vs[32 * PITCH];

    const int e0   = blockIdx.x * 128;
    const int ks   = blockIdx.y;
    const int k0   = ks * KTILE;
    const int tid  = threadIdx.x;
    const int lane = tid & 31;
    const int warp = tid >> 5;

    // --- cp.async W tile: 128 rows x 16 f4-chunks = 2048, 8 per thread.
    //     tid-contiguous kc within a row -> coalesced 128B segments.
    #pragma unroll
    for (int r = 0; r < 8; r++) {
        const int cid = tid + r * 256;
        const int e   = cid >> 4;
        const int kc  = cid & 15;
        const float* src = w + (size_t)(e0 + e) * CTOT + k0 + kc * 4;
        unsigned dst = (unsigned)__cvta_generic_to_shared(&ws[e * PITCH + kc * 4]);
        asm volatile("cp.async.cg.shared.global [%0], [%1], 16;\n"
                     :: "r"(dst), "l"(src));
    }
    asm volatile("cp.async.commit_group;\n");

    // --- v slice [32][64]: 512 f4, 2 per thread ---
    #pragma unroll
    for (int r = 0; r < 2; r++) {
        const int i  = tid + r * 256;
        const int b  = i >> 4;
        const int kq = i & 15;
        float4 v4 = *(const float4*)&g_v[b * CTOT + k0 + kq * 4];
        *(float4*)&vs[b * PITCH + kq * 4] = v4;
    }

    asm volatile("cp.async.wait_group 0;\n" ::: "memory");
    __syncthreads();

    // --- compute: warp covers 4 b, lane covers 4 e (stride 32) ---
    const int b0 = warp * 4;

    unsigned long long acc[4][4];   // [b_i][e_j]
    #pragma unroll
    for (int i = 0; i < 4; i++)
        #pragma unroll
        for (int j = 0; j < 4; j++) acc[i][j] = 0ull;

    #pragma unroll
    for (int k4 = 0; k4 < 16; k4++) {
        float4 wv[4];
        #pragma unroll
        for (int j = 0; j < 4; j++)
            wv[j] = *(const float4*)&ws[(lane + 32 * j) * PITCH + k4 * 4];
        #pragma unroll
        for (int i = 0; i < 4; i++) {
            float4 av = *(const float4*)&vs[(b0 + i) * PITCH + k4 * 4];
            const unsigned long long* ap = (const unsigned long long*)&av;
            #pragma unroll
            for (int j = 0; j < 4; j++) {
                const unsigned long long* wp = (const unsigned long long*)&wv[j];
                ffma2(acc[i][j], ap[0], wp[0]);
                ffma2(acc[i][j], ap[1], wp[1]);
            }
        }
    }

    // --- write partials: lane-contiguous e -> coalesced STG.32 ---
    #pragma unroll
    for (int i = 0; i < 4; i++) {
        #pragma unroll
        for (int j = 0; j < 4; j++) {
            float2 r2 = *(const float2*)&acc[i][j];
            g_part[ks][b0 + i][e0 + lane + 32 * j] = r2.x + r2.y;
        }
    }
}

// ---------------------------------------------------------------------------
// GEMM stage-2: sum the 60 partials per output (L2-resident).
// ---------------------------------------------------------------------------
__global__ __launch_bounds__(256)
void gemm_reduce_kernel(float* __restrict__ out) {
    const int idx = blockIdx.x * 256 + threadIdx.x;   // 0..32767
    const int b = idx >> 10;
    const int e = idx & 1023;
    float s = 0.f;
    #pragma unroll
    for (int k = 0; k < KSPLIT; k++)
        s += g_part[k][b][e];
    out[idx] = s;
}

// ---------------------------------------------------------------------------
extern "C" void kernel_launch(void* const* d_in, const int* in_sizes, int n_in,
                              void* d_out, int out_size) {
    const float* feat0  = (const float*)d_in[0];
    const float* feat1  = (const float*)d_in[1];
    const float* feat2  = (const float*)d_in[2];
    const float* feat3  = (const float*)d_in[3];
    const float* conv_w = (const float*)d_in[4];
    float* out = (float*)d_out;

    fused_pool_kernel<<<NBLK_TOTAL, 256>>>(feat0, feat1, feat2, feat3);

    gemm_part_kernel<<<dim3(8, KSPLIT), 256>>>(conv_w);

    gemm_reduce_kernel<<<128, 256>>>(out);
}

// round 15
// speedup vs baseline: 1.6506x; 1.0546x over previous
#include <cuda_runtime.h>
#include <cuda_bf16.h>
#include <cstdint>

// ---------------------------------------------------------------------------
// out[32,1024] = concat_c( spatial_mean(feat_l) ) @ conv_w.T
// (bilinear half-pixel upsample at ratios 1,2,4,8 + mean == plain mean.)
// feat0 [32,256,56,56], feat1 [32,512,28,28], feat2 [32,1024,14,14],
// feat3 [32,2048,7,7], conv_w [1024,3840].
//
// Sequential 3-kernel pipeline:
//  1) fused pool (HBM roofline; __ldcs evict-first on read-once feats)
//  2) GEMM stage-1: coalesced cp.async W->smem; warp = 8b x 64e-half
//     (4x smem amplification, was 8x); f32x2 8b x 2e microtile;
//     unroll 4 + launch_bounds(256,3) to stop spill pressure;
//     split-K partials, no atomics
//  3) stage-2: sum 60 L2-resident partials per output
// ---------------------------------------------------------------------------

#define BATCH 32
#define CTOT  3840
#define EMB   1024

#define KSPLIT 60
#define KTILE  64
#define PITCH  68          // 68 mod 32 = 4 -> conflict-free LDS.128 phases

__device__ float g_v[BATCH * CTOT];                 // pooled vector
__device__ float g_part[KSPLIT][BATCH][EMB];        // split-K partials (7.9MB)

__device__ __forceinline__ float warp_reduce(float s) {
    #pragma unroll
    for (int o = 16; o > 0; o >>= 1)
        s += __shfl_down_sync(0xFFFFFFFFu, s, o);
    return s;
}

__device__ __forceinline__ void ffma2(unsigned long long& d,
                                      unsigned long long a,
                                      unsigned long long b) {
    asm("fma.rn.f32x2 %0, %1, %2, %0;" : "+l"(d) : "l"(a), "l"(b));
}

// ---------------------------------------------------------------------------
// Fused pooling kernel (structure proven at 75.5% DRAM; loads now __ldcs).
// ---------------------------------------------------------------------------
#define NBLK0 1024
#define NBLK1 1024
#define NBLK2 2048
#define NBLK3 2048
#define NBLK_TOTAL (NBLK0 + NBLK1 + NBLK2 + NBLK3)

__global__ __launch_bounds__(256)
void fused_pool_kernel(const float* __restrict__ f0,
                       const float* __restrict__ f1,
                       const float* __restrict__ f2,
                       const float* __restrict__ f3) {
    const int blk  = blockIdx.x;
    const int lane = threadIdx.x & 31;
    const int warp = threadIdx.x >> 5;

    if (blk < NBLK0) {
        // ---- level 0: 56x56 = 784 f4, 1 plane per warp ----
        const int plane = blk * 8 + warp;
        const float4* __restrict__ p = (const float4*)f0 + (size_t)plane * 784;
        float a0 = 0.f, a1 = 0.f, a2 = 0.f, a3 = 0.f;
        #pragma unroll
        for (int k = 0; k < 6; k++) {
            float4 v0 = __ldcs(&p[lane + (4 * k + 0) * 32]);
            float4 v1 = __ldcs(&p[lane + (4 * k + 1) * 32]);
            float4 v2 = __ldcs(&p[lane + (4 * k + 2) * 32]);
            float4 v3 = __ldcs(&p[lane + (4 * k + 3) * 32]);
            a0 += (v0.x + v0.y) + (v0.z + v0.w);
            a1 += (v1.x + v1.y) + (v1.z + v1.w);
            a2 += (v2.x + v2.y) + (v2.z + v2.w);
            a3 += (v3.x + v3.y) + (v3.z + v3.w);
        }
        if (lane < 16) {
            float4 v = __ldcs(&p[768 + lane]);
            a0 += (v.x + v.y) + (v.z + v.w);
        }
        float s = warp_reduce((a0 + a1) + (a2 + a3));
        if (lane == 0) {
            const int b = plane >> 8, c = plane & 255;      // C=256
            g_v[b * CTOT + c] = s * (1.f / 3136.f);
        }
    } else if (blk < NBLK0 + NBLK1) {
        // ---- level 1: 28x28 = 196 f4, 2 planes per warp ----
        const int g = (blk - NBLK0) * 8 + warp;
        const int plane0 = g * 2;
        const float4* __restrict__ p = (const float4*)f1 + (size_t)plane0 * 196;
        float s0 = 0.f, s1 = 0.f;
        #pragma unroll
        for (int k = 0; k < 6; k++) {
            float4 v0 = __ldcs(&p[lane + k * 32]);
            float4 v1 = __ldcs(&p[196 + lane + k * 32]);
            s0 += (v0.x + v0.y) + (v0.z + v0.w);
            s1 += (v1.x + v1.y) + (v1.z + v1.w);
        }
        if (lane < 4) {
            float4 v0 = __ldcs(&p[192 + lane]);
            float4 v1 = __ldcs(&p[196 + 192 + lane]);
            s0 += (v0.x + v0.y) + (v0.z + v0.w);
            s1 += (v1.x + v1.y) + (v1.z + v1.w);
        }
        s0 = warp_reduce(s0);
        s1 = warp_reduce(s1);
        if (lane == 0) {
            const int b = plane0 >> 9, c = plane0 & 511;    // C=512
            g_v[b * CTOT + 256 + c]     = s0 * (1.f / 784.f);
            g_v[b * CTOT + 256 + c + 1] = s1 * (1.f / 784.f);
        }
    } else if (blk < NBLK0 + NBLK1 + NBLK2) {
        // ---- level 2: 14x14 = 49 f4, 2 planes per warp ----
        const int g = (blk - NBLK0 - NBLK1) * 8 + warp;
        const int plane0 = g * 2;
        const float4* __restrict__ p = (const float4*)f2 + (size_t)plane0 * 49;
        float s0, s1;
        {
            float4 v0 = __ldcs(&p[lane]);
            float4 v1 = __ldcs(&p[49 + lane]);
            s0 = (v0.x + v0.y) + (v0.z + v0.w);
            s1 = (v1.x + v1.y) + (v1.z + v1.w);
        }
        if (lane < 17) {
            float4 v0 = __ldcs(&p[32 + lane]);
            float4 v1 = __ldcs(&p[49 + 32 + lane]);
            s0 += (v0.x + v0.y) + (v0.z + v0.w);
            s1 += (v1.x + v1.y) + (v1.z + v1.w);
        }
        s0 = warp_reduce(s0);
        s1 = warp_reduce(s1);
        if (lane == 0) {
            const int b = plane0 >> 10, c = plane0 & 1023;  // C=1024
            g_v[b * CTOT + 768 + c]     = s0 * (1.f / 196.f);
            g_v[b * CTOT + 768 + c + 1] = s1 * (1.f / 196.f);
        }
    } else {
        // ---- level 3: 7x7 planes; warp handles 4 planes = 49 f4 ----
        const int g = (blk - NBLK0 - NBLK1 - NBLK2) * 8 + warp;
        const float4* __restrict__ p = (const float4*)f3 + (size_t)g * 49;

        float a0 = 0.f, a1 = 0.f, a2 = 0.f, a3 = 0.f;
        #pragma unroll
        for (int rep = 0; rep < 2; rep++) {
            const int i = lane + rep * 32;
            if (i < 49) {
                float4 v = __ldcs(&p[i]);
                const int e = 4 * i;
                {
                    int pl = e / 49; float x = v.x;
                    if (pl == 0) a0 += x; else if (pl == 1) a1 += x;
                    else if (pl == 2) a2 += x; else a3 += x;
                }
                {
                    int pl = (e + 1) / 49; float x = v.y;
                    if (pl == 0) a0 += x; else if (pl == 1) a1 += x;
                    else if (pl == 2) a2 += x; else a3 += x;
                }
                {
                    int pl = (e + 2) / 49; float x = v.z;
                    if (pl == 0) a0 += x; else if (pl == 1) a1 += x;
                    else if (pl == 2) a2 += x; else a3 += x;
                }
                {
                    int pl = (e + 3) / 49; float x = v.w;
                    if (pl == 0) a0 += x; else if (pl == 1) a1 += x;
                    else if (pl == 2) a2 += x; else a3 += x;
                }
            }
        }
        a0 = warp_reduce(a0);
        a1 = warp_reduce(a1);
        a2 = warp_reduce(a2);
        a3 = warp_reduce(a3);
        if (lane == 0) {
            const int plane0 = g * 4;
            const int b = plane0 >> 11, c = plane0 & 2047;  // C=2048
            float* dst = &g_v[b * CTOT + 1792 + c];
            dst[0] = a0 * (1.f / 49.f);
            dst[1] = a1 * (1.f / 49.f);
            dst[2] = a2 * (1.f / 49.f);
            dst[3] = a3 * (1.f / 49.f);
        }
    }
}

// ---------------------------------------------------------------------------
// GEMM stage-1: grid (8 e-tiles, 60 k-splits), 256 threads, 3 blocks/SM.
// Warp w: b-quarter = (w&3)*8, e-half = (w>>2)*64 — each warp only touches
// its own 64-e half of ws (4x amplification, was 8x). Microtile 8b x 2e,
// f32x2 along K. Disjoint partial outputs (no atomics).
// ---------------------------------------------------------------------------
__global__ __launch_bounds__(256, 3)
void gemm_part_kernel(const float* __restrict__ w) {
    __shared__ float ws[128 * PITCH];
    __shared__ float vs[32 * PITCH];

    const int e0   = blockIdx.x * 128;
    const int ks   = blockIdx.y;
    const int k0   = ks * KTILE;
    const int tid  = threadIdx.x;
    const int lane = tid & 31;
    const int warp = tid >> 5;

    // --- cp.async W tile: 128 rows x 16 f4-chunks = 2048, 8 per thread ---
    #pragma unroll
    for (int r = 0; r < 8; r++) {
        const int cid = tid + r * 256;
        const int e   = cid >> 4;
        const int kc  = cid & 15;
        const float* src = w + (size_t)(e0 + e) * CTOT + k0 + kc * 4;
        unsigned dst = (unsigned)__cvta_generic_to_shared(&ws[e * PITCH + kc * 4]);
        asm volatile("cp.async.cg.shared.global [%0], [%1], 16;\n"
                     :: "r"(dst), "l"(src));
    }
    asm volatile("cp.async.commit_group;\n");

    // --- v slice [32][64]: 512 f4, 2 per thread ---
    #pragma unroll
    for (int r = 0; r < 2; r++) {
        const int i  = tid + r * 256;
        const int b  = i >> 4;
        const int kq = i & 15;
        float4 v4 = *(const float4*)&g_v[b * CTOT + k0 + kq * 4];
        *(float4*)&vs[b * PITCH + kq * 4] = v4;
    }

    asm volatile("cp.async.wait_group 0;\n" ::: "memory");
    __syncthreads();

    // --- compute: warp = 8b x 64e-half; thread microtile 8b x 2e ---
    const int b0 = (warp & 3) * 8;
    const int c1 = ((warp >> 2) << 6) + lane;        // e-col 1 (0..127)
    const int c2 = c1 + 32;                          // e-col 2

    unsigned long long acc[8][2];
    #pragma unroll
    for (int i = 0; i < 8; i++) { acc[i][0] = 0ull; acc[i][1] = 0ull; }

    #pragma unroll 4
    for (int k4 = 0; k4 < 16; k4++) {
        float4 wv0 = *(const float4*)&ws[c1 * PITCH + k4 * 4];
        float4 wv1 = *(const float4*)&ws[c2 * PITCH + k4 * 4];
        const unsigned long long* wp0 = (const unsigned long long*)&wv0;
        const unsigned long long* wp1 = (const unsigned long long*)&wv1;
        #pragma unroll
        for (int i = 0; i < 8; i++) {
            float4 av = *(const float4*)&vs[(b0 + i) * PITCH + k4 * 4];  // bcast
            const unsigned long long* ap = (const unsigned long long*)&av;
            ffma2(acc[i][0], ap[0], wp0[0]);
            ffma2(acc[i][0], ap[1], wp0[1]);
            ffma2(acc[i][1], ap[0], wp1[0]);
            ffma2(acc[i][1], ap[1], wp1[1]);
        }
    }

    // --- write partials: lane-contiguous e -> coalesced STG.32 ---
    #pragma unroll
    for (int i = 0; i < 8; i++) {
        float2 r0 = *(const float2*)&acc[i][0];
        float2 r1 = *(const float2*)&acc[i][1];
        g_part[ks][b0 + i][e0 + c1] = r0.x + r0.y;
        g_part[ks][b0 + i][e0 + c2] = r1.x + r1.y;
    }
}

// ---------------------------------------------------------------------------
// GEMM stage-2: sum the 60 partials per output (L2-resident).
// ---------------------------------------------------------------------------
__global__ __launch_bounds__(256)
void gemm_reduce_kernel(float* __restrict__ out) {
    const int idx = blockIdx.x * 256 + threadIdx.x;   // 0..32767
    const int b = idx >> 10;
    const int e = idx & 1023;
    float s = 0.f;
    #pragma unroll
    for (int k = 0; k < KSPLIT; k++)
        s += g_part[k][b][e];
    out[idx] = s;
}

// ---------------------------------------------------------------------------
extern "C" void kernel_launch(void* const* d_in, const int* in_sizes, int n_in,
                              void* d_out, int out_size) {
    const float* feat0  = (const float*)d_in[0];
    const float* feat1  = (const float*)d_in[1];
    const float* feat2  = (const float*)d_in[2];
    const float* feat3  = (const float*)d_in[3];
    const float* conv_w = (const float*)d_in[4];
    float* out = (float*)d_out;

    fused_pool_kernel<<<NBLK_TOTAL, 256>>>(feat0, feat1, feat2, feat3);

    gemm_part_kernel<<<dim3(8, KSPLIT), 256>>>(conv_w);

    gemm_reduce_kernel<<<128, 256>>>(out);
}